// round 2
// baseline (speedup 1.0000x reference)
#include <cuda_runtime.h>
#include <math.h>

#define GRES 64
#define GR3 (GRES*GRES*GRES)
#define MAXB 8

// Intermediates (per batch): joints, per-joint affine rows, pose_map
__device__ float g_joints[MAXB * 24 * 3];
__device__ float g_A[MAXB * 24 * 12];     // [b][joint][row d:0..2][R0 R1 R2 t']
__device__ float g_pm[MAXB * 207];

__constant__ int c_parents[24] = {-1,0,0,0,1,2,3,4,5,6,7,8,9,9,9,12,13,14,16,17,18,19,20,21};

// ---------------------------------------------------------------------------
// Kernel 1: joints j[b,24,3] = J_regressor @ (v_template + shapedirs @ beta)
// grid (24, B), 256 threads
// ---------------------------------------------------------------------------
__global__ void joints_kernel(const float* __restrict__ beta,
                              const float* __restrict__ vt,
                              const float* __restrict__ sd,   // [6890,3,10]
                              const float* __restrict__ JR)   // [24,6890]
{
    int jt = blockIdx.x, b = blockIdx.y;
    int tid = threadIdx.x;
    __shared__ float sb[10];
    if (tid < 10) sb[tid] = beta[b * 10 + tid];
    __syncthreads();
    float bb[10];
#pragma unroll
    for (int k = 0; k < 10; k++) bb[k] = sb[k];

    float a0 = 0.f, a1 = 0.f, a2 = 0.f;
    for (int v = tid; v < 6890; v += blockDim.x) {
        float w = JR[jt * 6890 + v];
        const float* sdp = sd + v * 30;
        float v0 = vt[v * 3 + 0], v1 = vt[v * 3 + 1], v2 = vt[v * 3 + 2];
#pragma unroll
        for (int k = 0; k < 10; k++) {
            v0 = fmaf(sdp[k],      bb[k], v0);
            v1 = fmaf(sdp[10 + k], bb[k], v1);
            v2 = fmaf(sdp[20 + k], bb[k], v2);
        }
        a0 = fmaf(w, v0, a0); a1 = fmaf(w, v1, a1); a2 = fmaf(w, v2, a2);
    }
    __shared__ float r0[256], r1[256], r2[256];
    r0[tid] = a0; r1[tid] = a1; r2[tid] = a2;
    __syncthreads();
    for (int s = blockDim.x / 2; s > 0; s >>= 1) {
        if (tid < s) { r0[tid] += r0[tid + s]; r1[tid] += r1[tid + s]; r2[tid] += r2[tid + s]; }
        __syncthreads();
    }
    if (tid == 0) {
        float* o = g_joints + (b * 24 + jt) * 3;
        o[0] = r0[0]; o[1] = r1[0]; o[2] = r2[0];
    }
}

// ---------------------------------------------------------------------------
// Kernel 2: rodrigues + pose_map + kinematic chain + final A rows
// grid (B), 32 threads
// ---------------------------------------------------------------------------
__global__ void transforms_kernel(const float* __restrict__ pose)
{
    int b = blockIdx.x;
    int i = threadIdx.x;
    __shared__ float rot[24][9];
    __shared__ float resR[24][9];
    __shared__ float resT[24][3];

    if (i < 24) {
        float rx = pose[b * 72 + i * 3 + 0];
        float ry = pose[b * 72 + i * 3 + 1];
        float rz = pose[b * 72 + i * 3 + 2];
        float th = sqrtf(rx * rx + ry * ry + rz * rz + 1e-12f);
        float inv = 1.f / th;
        float x = rx * inv, y = ry * inv, z = rz * inv;
        float s = sinf(th), c = cosf(th), t = 1.f - c;
        rot[i][0] = c + t * x * x;     rot[i][1] = t * x * y - s * z; rot[i][2] = t * x * z + s * y;
        rot[i][3] = t * x * y + s * z; rot[i][4] = c + t * y * y;     rot[i][5] = t * y * z - s * x;
        rot[i][6] = t * x * z - s * y; rot[i][7] = t * y * z + s * x; rot[i][8] = c + t * z * z;
    }
    __syncthreads();

    if (i >= 1 && i < 24) {
#pragma unroll
        for (int e = 0; e < 9; e++)
            g_pm[b * 207 + (i - 1) * 9 + e] = rot[i][e] - ((e == 0 || e == 4 || e == 8) ? 1.f : 0.f);
    }

    if (i == 0) {
        const float* J = g_joints + b * 72;
#pragma unroll
        for (int e = 0; e < 9; e++) resR[0][e] = rot[0][e];
        resT[0][0] = J[0]; resT[0][1] = J[1]; resT[0][2] = J[2];
        for (int jt = 1; jt < 24; jt++) {
            int p = c_parents[jt];
            float t0 = J[jt * 3 + 0] - J[p * 3 + 0];
            float t1 = J[jt * 3 + 1] - J[p * 3 + 1];
            float t2 = J[jt * 3 + 2] - J[p * 3 + 2];
            for (int r = 0; r < 3; r++) {
                float p0 = resR[p][r * 3 + 0], p1 = resR[p][r * 3 + 1], p2 = resR[p][r * 3 + 2];
                for (int cc = 0; cc < 3; cc++)
                    resR[jt][r * 3 + cc] = p0 * rot[jt][0 + cc] + p1 * rot[jt][3 + cc] + p2 * rot[jt][6 + cc];
                resT[jt][r] = p0 * t0 + p1 * t1 + p2 * t2 + resT[p][r];
            }
        }
        for (int jt = 0; jt < 24; jt++) {
            float jx = J[jt * 3 + 0], jy = J[jt * 3 + 1], jz = J[jt * 3 + 2];
            float* o = g_A + b * 288 + jt * 12;
            for (int r = 0; r < 3; r++) {
                float R0 = resR[jt][r * 3 + 0], R1 = resR[jt][r * 3 + 1], R2 = resR[jt][r * 3 + 2];
                o[r * 4 + 0] = R0; o[r * 4 + 1] = R1; o[r * 4 + 2] = R2;
                o[r * 4 + 3] = resT[jt][r] - (R0 * jx + R1 * jy + R2 * jz);
            }
        }
    }
}

// ---------------------------------------------------------------------------
// Trilinear 8-corner gather for one channel slab
// ---------------------------------------------------------------------------
__device__ __forceinline__ float samp8(const float* __restrict__ g,
                                       const int* o, const float* w)
{
    float s00 = fmaf(w[0], __ldg(g + o[0]), w[1] * __ldg(g + o[1]));
    float s01 = fmaf(w[2], __ldg(g + o[2]), w[3] * __ldg(g + o[3]));
    float s10 = fmaf(w[4], __ldg(g + o[4]), w[5] * __ldg(g + o[5]));
    float s11 = fmaf(w[6], __ldg(g + o[6]), w[7] * __ldg(g + o[7]));
    return (s00 + s01) + (s10 + s11);
}

// ---------------------------------------------------------------------------
// Main kernel: one thread per point; 678-channel gather + fused epilogue
// ---------------------------------------------------------------------------
__global__ void __launch_bounds__(256) main_kernel(
    const float* __restrict__ points,
    const float* __restrict__ beta,
    const float* __restrict__ trans,
    const float* __restrict__ scale_p,
    const float* __restrict__ center,
    const float* __restrict__ closest,
    const float* __restrict__ shd,
    const float* __restrict__ pdirs,
    const float* __restrict__ skin,
    float* __restrict__ out,
    int N, int total)
{
    __shared__ float s_pm[207];
    __shared__ float s_A[288];
    __shared__ float s_beta[10];

    int t = blockIdx.x * blockDim.x + threadIdx.x;
    int b = (blockIdx.x * (int)blockDim.x) / N;   // N % blockDim == 0 for this dataset

    for (int k = threadIdx.x; k < 207; k += blockDim.x) s_pm[k] = g_pm[b * 207 + k];
    for (int k = threadIdx.x; k < 288; k += blockDim.x) s_A[k]  = g_A[b * 288 + k];
    if (threadIdx.x < 10) s_beta[threadIdx.x] = beta[b * 10 + threadIdx.x];
    __syncthreads();

    if (t >= total) return;

    float scale = *scale_p;
    float px = fmaf(points[t * 3 + 0], scale, center[0]);
    float py = fmaf(points[t * 3 + 1], scale, center[1]);
    float pz = fmaf(points[t * 3 + 2], scale, center[2]);

    // grid_sample coords, align_corners=False
    float cx = ((px + 1.f) * (float)GRES - 1.f) * 0.5f;
    float cy = ((py + 1.f) * (float)GRES - 1.f) * 0.5f;
    float cz = ((pz + 1.f) * (float)GRES - 1.f) * 0.5f;

    float fx = floorf(cx), fy = floorf(cy), fz = floorf(cz);
    int ix = (int)fx, iy = (int)fy, iz = (int)fz;
    float ux = cx - fx, uy = cy - fy, uz = cz - fz;

    float wx[2], wy[2], wz[2];
    int xi[2], yi[2], zi[2];
    wx[0] = (ix >= 0 && ix < GRES)         ? (1.f - ux) : 0.f;
    wx[1] = (ix + 1 >= 0 && ix + 1 < GRES) ? ux         : 0.f;
    wy[0] = (iy >= 0 && iy < GRES)         ? (1.f - uy) : 0.f;
    wy[1] = (iy + 1 >= 0 && iy + 1 < GRES) ? uy         : 0.f;
    wz[0] = (iz >= 0 && iz < GRES)         ? (1.f - uz) : 0.f;
    wz[1] = (iz + 1 >= 0 && iz + 1 < GRES) ? uz         : 0.f;
    xi[0] = min(max(ix, 0), GRES - 1);     xi[1] = min(max(ix + 1, 0), GRES - 1);
    yi[0] = min(max(iy, 0), GRES - 1);     yi[1] = min(max(iy + 1, 0), GRES - 1);
    zi[0] = min(max(iz, 0), GRES - 1);     zi[1] = min(max(iz + 1, 0), GRES - 1);

    int o[8]; float w[8];
#pragma unroll
    for (int dx = 0; dx < 2; dx++)
#pragma unroll
        for (int dy = 0; dy < 2; dy++)
#pragma unroll
            for (int dz = 0; dz < 2; dz++) {
                int idx = dx * 4 + dy * 2 + dz;
                o[idx] = (xi[dx] * GRES + yi[dy]) * GRES + zi[dz];
                w[idx] = wx[dx] * wy[dy] * wz[dz];
            }

    float a[3];
    // closest (3 channels)
#pragma unroll
    for (int d = 0; d < 3; d++) a[d] = samp8(closest + d * GR3, o, w);

    // shapedirs (30 channels: [3][10]) dot beta
#pragma unroll
    for (int d = 0; d < 3; d++) {
        const float* g = shd + d * 10 * GR3;
        float acc = 0.f;
#pragma unroll 2
        for (int k = 0; k < 10; k++) { acc = fmaf(samp8(g, o, w), s_beta[k], acc); g += GR3; }
        a[d] += acc;
    }

    // posedirs (621 channels: [3][207]) dot pose_map
#pragma unroll
    for (int d = 0; d < 3; d++) {
        const float* g = pdirs + d * 207 * GR3;
        float acc = 0.f;
#pragma unroll 2
        for (int k = 0; k < 207; k++) { acc = fmaf(samp8(g, o, w), s_pm[k], acc); g += GR3; }
        a[d] += acc;
    }

    // skin (24 channels) blended with per-joint affine, fused into output accum
    float ox = 0.f, oy = 0.f, oz = 0.f;
    {
        const float* g = skin;
#pragma unroll 2
        for (int j = 0; j < 24; j++) {
            float s = samp8(g, o, w);
            g += GR3;
            const float* Aj = s_A + j * 12;
            ox = fmaf(s, fmaf(Aj[0], a[0], fmaf(Aj[1], a[1], fmaf(Aj[2],  a[2], Aj[3]))),  ox);
            oy = fmaf(s, fmaf(Aj[4], a[0], fmaf(Aj[5], a[1], fmaf(Aj[6],  a[2], Aj[7]))),  oy);
            oz = fmaf(s, fmaf(Aj[8], a[0], fmaf(Aj[9], a[1], fmaf(Aj[10], a[2], Aj[11]))), oz);
        }
    }

    out[t * 3 + 0] = ox + trans[b * 3 + 0];
    out[t * 3 + 1] = oy + trans[b * 3 + 1];
    out[t * 3 + 2] = oz + trans[b * 3 + 2];
}

// ---------------------------------------------------------------------------
extern "C" void kernel_launch(void* const* d_in, const int* in_sizes, int n_in,
                              void* d_out, int out_size)
{
    const float* points  = (const float*)d_in[0];
    const float* pose    = (const float*)d_in[1];
    const float* beta    = (const float*)d_in[2];
    const float* trans   = (const float*)d_in[3];
    const float* scale   = (const float*)d_in[4];
    const float* center  = (const float*)d_in[5];
    const float* closest = (const float*)d_in[6];
    const float* shd     = (const float*)d_in[7];
    const float* pdirs   = (const float*)d_in[8];
    const float* skin    = (const float*)d_in[9];
    const float* vt      = (const float*)d_in[10];
    const float* sd      = (const float*)d_in[11];
    const float* JR      = (const float*)d_in[12];

    int B = in_sizes[1] / 72;
    int N = in_sizes[0] / (3 * B);
    int total = B * N;

    dim3 jg(24, B);
    joints_kernel<<<jg, 256>>>(beta, vt, sd, JR);
    transforms_kernel<<<B, 32>>>(pose);

    int blocks = (total + 255) / 256;
    main_kernel<<<blocks, 256>>>(points, beta, trans, scale, center,
                                 closest, shd, pdirs, skin,
                                 (float*)d_out, N, total);
}

// round 3
// speedup vs baseline: 1.7233x; 1.7233x over previous
#include <cuda_runtime.h>
#include <math.h>

#define GRES 64
#define GR3 (GRES*GRES*GRES)
#define MAXB 8
#define NBINS 32768          // 32^3 morton cells
#define MAXPTS (1<<18)

__device__ float g_joints[MAXB * 24 * 3];
__device__ float g_A[MAXB * 24 * 12];
__device__ float g_pm[MAXB * 207];
__device__ float g_vsh[MAXB * 6890 * 3];
__device__ unsigned int g_hist[NBINS];
__device__ unsigned int g_off[NBINS];
__device__ int g_perm[MAXPTS];

__constant__ int c_parents[24] = {-1,0,0,0,1,2,3,4,5,6,7,8,9,9,9,12,13,14,16,17,18,19,20,21};

// ---------------------------------------------------------------------------
// Spatial key: morton code of the 32^3 cell containing the floor voxel
// ---------------------------------------------------------------------------
__device__ __forceinline__ int point_key(const float* __restrict__ points, int p,
                                         float scale, float c0, float c1, float c2)
{
    float px = fmaf(points[p * 3 + 0], scale, c0);
    float py = fmaf(points[p * 3 + 1], scale, c1);
    float pz = fmaf(points[p * 3 + 2], scale, c2);
    float cx = ((px + 1.f) * (float)GRES - 1.f) * 0.5f;
    float cy = ((py + 1.f) * (float)GRES - 1.f) * 0.5f;
    float cz = ((pz + 1.f) * (float)GRES - 1.f) * 0.5f;
    int ix = (int)floorf(cx), iy = (int)floorf(cy), iz = (int)floorf(cz);
    unsigned x = (unsigned)(min(max(ix, 0), 63)) >> 1;
    unsigned y = (unsigned)(min(max(iy, 0), 63)) >> 1;
    unsigned z = (unsigned)(min(max(iz, 0), 63)) >> 1;
    unsigned key = 0;
#pragma unroll
    for (int b = 0; b < 5; b++) {
        key |= ((x >> b) & 1u) << (3 * b + 2);
        key |= ((y >> b) & 1u) << (3 * b + 1);
        key |= ((z >> b) & 1u) << (3 * b + 0);
    }
    return (int)key;
}

__global__ void zero_hist_kernel() {
    int i = blockIdx.x * blockDim.x + threadIdx.x;
    if (i < NBINS) g_hist[i] = 0u;
}

__global__ void hist_kernel(const float* __restrict__ points,
                            const float* __restrict__ scale_p,
                            const float* __restrict__ center, int total)
{
    int p = blockIdx.x * blockDim.x + threadIdx.x;
    if (p >= total) return;
    int key = point_key(points, p, *scale_p, center[0], center[1], center[2]);
    atomicAdd(&g_hist[key], 1u);
}

// Exclusive scan of g_hist -> g_off. One block of 1024 threads, 32 bins each.
__global__ void scan_kernel()
{
    __shared__ unsigned int ssum[1024];
    int tid = threadIdx.x;
    unsigned int local[32];
    unsigned int s = 0;
#pragma unroll
    for (int i = 0; i < 32; i++) { local[i] = s; s += g_hist[tid * 32 + i]; }
    ssum[tid] = s;
    __syncthreads();
    // Hillis-Steele inclusive scan on ssum
    for (int st = 1; st < 1024; st <<= 1) {
        unsigned int v = (tid >= st) ? ssum[tid - st] : 0u;
        __syncthreads();
        ssum[tid] += v;
        __syncthreads();
    }
    unsigned int base = (tid == 0) ? 0u : ssum[tid - 1];
#pragma unroll
    for (int i = 0; i < 32; i++) g_off[tid * 32 + i] = base + local[i];
}

__global__ void scatter_kernel(const float* __restrict__ points,
                               const float* __restrict__ scale_p,
                               const float* __restrict__ center, int total)
{
    int p = blockIdx.x * blockDim.x + threadIdx.x;
    if (p >= total) return;
    int key = point_key(points, p, *scale_p, center[0], center[1], center[2]);
    unsigned int pos = atomicAdd(&g_off[key], 1u);
    g_perm[pos] = p;
}

// ---------------------------------------------------------------------------
// v_shaped[b,v,:] = v_template[v] + shapedirs[v] @ beta[b]   (reads sd once/b)
// ---------------------------------------------------------------------------
__global__ void vshape_kernel(const float* __restrict__ beta,
                              const float* __restrict__ vt,
                              const float* __restrict__ sd, int B)
{
    int i = blockIdx.x * blockDim.x + threadIdx.x;
    int v = i % 6890, b = i / 6890;
    if (b >= B) return;
    const float* bb = beta + b * 10;
    const float* sdp = sd + v * 30;
    float v0 = vt[v * 3 + 0], v1 = vt[v * 3 + 1], v2 = vt[v * 3 + 2];
#pragma unroll
    for (int k = 0; k < 10; k++) {
        float bk = __ldg(bb + k);
        v0 = fmaf(sdp[k],      bk, v0);
        v1 = fmaf(sdp[10 + k], bk, v1);
        v2 = fmaf(sdp[20 + k], bk, v2);
    }
    float* o = g_vsh + (b * 6890 + v) * 3;
    o[0] = v0; o[1] = v1; o[2] = v2;
}

__global__ void joints_kernel(const float* __restrict__ JR)
{
    int jt = blockIdx.x, b = blockIdx.y;
    int tid = threadIdx.x;
    float a0 = 0.f, a1 = 0.f, a2 = 0.f;
    const float* vsh = g_vsh + b * 6890 * 3;
    for (int v = tid; v < 6890; v += blockDim.x) {
        float w = JR[jt * 6890 + v];
        a0 = fmaf(w, vsh[v * 3 + 0], a0);
        a1 = fmaf(w, vsh[v * 3 + 1], a1);
        a2 = fmaf(w, vsh[v * 3 + 2], a2);
    }
    __shared__ float r0[256], r1[256], r2[256];
    r0[tid] = a0; r1[tid] = a1; r2[tid] = a2;
    __syncthreads();
    for (int s = blockDim.x / 2; s > 0; s >>= 1) {
        if (tid < s) { r0[tid] += r0[tid + s]; r1[tid] += r1[tid + s]; r2[tid] += r2[tid + s]; }
        __syncthreads();
    }
    if (tid == 0) {
        float* o = g_joints + (b * 24 + jt) * 3;
        o[0] = r0[0]; o[1] = r1[0]; o[2] = r2[0];
    }
}

// ---------------------------------------------------------------------------
// rodrigues + pose_map + kinematic chain + final A rows
// ---------------------------------------------------------------------------
__global__ void transforms_kernel(const float* __restrict__ pose)
{
    int b = blockIdx.x;
    int i = threadIdx.x;
    __shared__ float rot[24][9];
    __shared__ float resR[24][9];
    __shared__ float resT[24][3];

    if (i < 24) {
        float rx = pose[b * 72 + i * 3 + 0];
        float ry = pose[b * 72 + i * 3 + 1];
        float rz = pose[b * 72 + i * 3 + 2];
        float th = sqrtf(rx * rx + ry * ry + rz * rz + 1e-12f);
        float inv = 1.f / th;
        float x = rx * inv, y = ry * inv, z = rz * inv;
        float s = sinf(th), c = cosf(th), t = 1.f - c;
        rot[i][0] = c + t * x * x;     rot[i][1] = t * x * y - s * z; rot[i][2] = t * x * z + s * y;
        rot[i][3] = t * x * y + s * z; rot[i][4] = c + t * y * y;     rot[i][5] = t * y * z - s * x;
        rot[i][6] = t * x * z - s * y; rot[i][7] = t * y * z + s * x; rot[i][8] = c + t * z * z;
    }
    __syncthreads();

    if (i >= 1 && i < 24) {
#pragma unroll
        for (int e = 0; e < 9; e++)
            g_pm[b * 207 + (i - 1) * 9 + e] = rot[i][e] - ((e == 0 || e == 4 || e == 8) ? 1.f : 0.f);
    }

    if (i == 0) {
        const float* J = g_joints + b * 72;
#pragma unroll
        for (int e = 0; e < 9; e++) resR[0][e] = rot[0][e];
        resT[0][0] = J[0]; resT[0][1] = J[1]; resT[0][2] = J[2];
        for (int jt = 1; jt < 24; jt++) {
            int p = c_parents[jt];
            float t0 = J[jt * 3 + 0] - J[p * 3 + 0];
            float t1 = J[jt * 3 + 1] - J[p * 3 + 1];
            float t2 = J[jt * 3 + 2] - J[p * 3 + 2];
            for (int r = 0; r < 3; r++) {
                float p0 = resR[p][r * 3 + 0], p1 = resR[p][r * 3 + 1], p2 = resR[p][r * 3 + 2];
                for (int cc = 0; cc < 3; cc++)
                    resR[jt][r * 3 + cc] = p0 * rot[jt][0 + cc] + p1 * rot[jt][3 + cc] + p2 * rot[jt][6 + cc];
                resT[jt][r] = p0 * t0 + p1 * t1 + p2 * t2 + resT[p][r];
            }
        }
        for (int jt = 0; jt < 24; jt++) {
            float jx = J[jt * 3 + 0], jy = J[jt * 3 + 1], jz = J[jt * 3 + 2];
            float* o = g_A + b * 288 + jt * 12;
            for (int r = 0; r < 3; r++) {
                float R0 = resR[jt][r * 3 + 0], R1 = resR[jt][r * 3 + 1], R2 = resR[jt][r * 3 + 2];
                o[r * 4 + 0] = R0; o[r * 4 + 1] = R1; o[r * 4 + 2] = R2;
                o[r * 4 + 3] = resT[jt][r] - (R0 * jx + R1 * jy + R2 * jz);
            }
        }
    }
}

// ---------------------------------------------------------------------------
__device__ __forceinline__ float samp8(const float* __restrict__ g,
                                       const int* o, const float* w)
{
    float s00 = fmaf(w[0], __ldg(g + o[0]), w[1] * __ldg(g + o[1]));
    float s01 = fmaf(w[2], __ldg(g + o[2]), w[3] * __ldg(g + o[3]));
    float s10 = fmaf(w[4], __ldg(g + o[4]), w[5] * __ldg(g + o[5]));
    float s11 = fmaf(w[6], __ldg(g + o[6]), w[7] * __ldg(g + o[7]));
    return (s00 + s01) + (s10 + s11);
}

// ---------------------------------------------------------------------------
// Main kernel: one thread per SORTED point; 678-channel gather + fused epilogue
// ---------------------------------------------------------------------------
__global__ void __launch_bounds__(256) main_kernel(
    const float* __restrict__ points,
    const float* __restrict__ beta,
    const float* __restrict__ trans,
    const float* __restrict__ scale_p,
    const float* __restrict__ center,
    const float* __restrict__ closest,
    const float* __restrict__ shd,
    const float* __restrict__ pdirs,
    const float* __restrict__ skin,
    float* __restrict__ out,
    int N, int B, int total)
{
    __shared__ float s_pm[MAXB][207];
    __shared__ float s_A[MAXB][288];
    __shared__ float s_beta[MAXB][10];
    __shared__ float s_trans[MAXB][3];

    // load per-batch constants for ALL batches (blocks now hold mixed batches)
    for (int k = threadIdx.x; k < B * 508; k += blockDim.x) {
        int bb = k / 508, r = k % 508;
        if (r < 207)      s_pm[bb][r]          = g_pm[bb * 207 + r];
        else if (r < 495) s_A[bb][r - 207]     = g_A[bb * 288 + (r - 207)];
        else if (r < 505) s_beta[bb][r - 495]  = beta[bb * 10 + (r - 495)];
        else              s_trans[bb][r - 505] = trans[bb * 3 + (r - 505)];
    }
    __syncthreads();

    int t = blockIdx.x * blockDim.x + threadIdx.x;
    if (t >= total) return;
    int p = g_perm[t];
    int b = p / N;

    float scale = *scale_p;
    float px = fmaf(points[p * 3 + 0], scale, center[0]);
    float py = fmaf(points[p * 3 + 1], scale, center[1]);
    float pz = fmaf(points[p * 3 + 2], scale, center[2]);

    float cx = ((px + 1.f) * (float)GRES - 1.f) * 0.5f;
    float cy = ((py + 1.f) * (float)GRES - 1.f) * 0.5f;
    float cz = ((pz + 1.f) * (float)GRES - 1.f) * 0.5f;

    float fx = floorf(cx), fy = floorf(cy), fz = floorf(cz);
    int ix = (int)fx, iy = (int)fy, iz = (int)fz;
    float ux = cx - fx, uy = cy - fy, uz = cz - fz;

    float wx[2], wy[2], wz[2];
    int xi[2], yi[2], zi[2];
    wx[0] = (ix >= 0 && ix < GRES)         ? (1.f - ux) : 0.f;
    wx[1] = (ix + 1 >= 0 && ix + 1 < GRES) ? ux         : 0.f;
    wy[0] = (iy >= 0 && iy < GRES)         ? (1.f - uy) : 0.f;
    wy[1] = (iy + 1 >= 0 && iy + 1 < GRES) ? uy         : 0.f;
    wz[0] = (iz >= 0 && iz < GRES)         ? (1.f - uz) : 0.f;
    wz[1] = (iz + 1 >= 0 && iz + 1 < GRES) ? uz         : 0.f;
    xi[0] = min(max(ix, 0), GRES - 1);     xi[1] = min(max(ix + 1, 0), GRES - 1);
    yi[0] = min(max(iy, 0), GRES - 1);     yi[1] = min(max(iy + 1, 0), GRES - 1);
    zi[0] = min(max(iz, 0), GRES - 1);     zi[1] = min(max(iz + 1, 0), GRES - 1);

    int o[8]; float w[8];
#pragma unroll
    for (int dx = 0; dx < 2; dx++)
#pragma unroll
        for (int dy = 0; dy < 2; dy++)
#pragma unroll
            for (int dz = 0; dz < 2; dz++) {
                int idx = dx * 4 + dy * 2 + dz;
                o[idx] = (xi[dx] * GRES + yi[dy]) * GRES + zi[dz];
                w[idx] = wx[dx] * wy[dy] * wz[dz];
            }

    float a[3];
#pragma unroll
    for (int d = 0; d < 3; d++) a[d] = samp8(closest + d * GR3, o, w);

#pragma unroll
    for (int d = 0; d < 3; d++) {
        const float* g = shd + d * 10 * GR3;
        float acc = 0.f;
#pragma unroll 2
        for (int k = 0; k < 10; k++) { acc = fmaf(samp8(g, o, w), s_beta[b][k], acc); g += GR3; }
        a[d] += acc;
    }

#pragma unroll
    for (int d = 0; d < 3; d++) {
        const float* g = pdirs + d * 207 * GR3;
        float acc = 0.f;
#pragma unroll 2
        for (int k = 0; k < 207; k++) { acc = fmaf(samp8(g, o, w), s_pm[b][k], acc); g += GR3; }
        a[d] += acc;
    }

    float ox = 0.f, oy = 0.f, oz = 0.f;
    {
        const float* g = skin;
#pragma unroll 2
        for (int j = 0; j < 24; j++) {
            float s = samp8(g, o, w);
            g += GR3;
            const float* Aj = &s_A[b][j * 12];
            ox = fmaf(s, fmaf(Aj[0], a[0], fmaf(Aj[1], a[1], fmaf(Aj[2],  a[2], Aj[3]))),  ox);
            oy = fmaf(s, fmaf(Aj[4], a[0], fmaf(Aj[5], a[1], fmaf(Aj[6],  a[2], Aj[7]))),  oy);
            oz = fmaf(s, fmaf(Aj[8], a[0], fmaf(Aj[9], a[1], fmaf(Aj[10], a[2], Aj[11]))), oz);
        }
    }

    out[p * 3 + 0] = ox + s_trans[b][0];
    out[p * 3 + 1] = oy + s_trans[b][1];
    out[p * 3 + 2] = oz + s_trans[b][2];
}

// ---------------------------------------------------------------------------
extern "C" void kernel_launch(void* const* d_in, const int* in_sizes, int n_in,
                              void* d_out, int out_size)
{
    const float* points  = (const float*)d_in[0];
    const float* pose    = (const float*)d_in[1];
    const float* beta    = (const float*)d_in[2];
    const float* trans   = (const float*)d_in[3];
    const float* scale   = (const float*)d_in[4];
    const float* center  = (const float*)d_in[5];
    const float* closest = (const float*)d_in[6];
    const float* shd     = (const float*)d_in[7];
    const float* pdirs   = (const float*)d_in[8];
    const float* skin    = (const float*)d_in[9];
    const float* vt      = (const float*)d_in[10];
    const float* sd      = (const float*)d_in[11];
    const float* JR      = (const float*)d_in[12];

    int B = in_sizes[1] / 72;
    int N = in_sizes[0] / (3 * B);
    int total = B * N;
    int pblocks = (total + 255) / 256;

    // spatial binning of points (counting sort by 32^3 morton cell)
    zero_hist_kernel<<<(NBINS + 255) / 256, 256>>>();
    hist_kernel<<<pblocks, 256>>>(points, scale, center, total);
    scan_kernel<<<1, 1024>>>();
    scatter_kernel<<<pblocks, 256>>>(points, scale, center, total);

    // SMPL skeleton math
    vshape_kernel<<<(6890 * B + 255) / 256, 256>>>(beta, vt, sd, B);
    dim3 jg(24, B);
    joints_kernel<<<jg, 256>>>(JR);
    transforms_kernel<<<B, 32>>>(pose);

    // fused gather + LBS
    main_kernel<<<pblocks, 256>>>(points, beta, trans, scale, center,
                                  closest, shd, pdirs, skin,
                                  (float*)d_out, N, B, total);
}